// round 1
// baseline (speedup 1.0000x reference)
#include <cuda_runtime.h>
#include <cuda_bf16.h>
#include <math.h>
#include <float.h>

// ---------------- problem constants ----------------
#define BB    8
#define NN    2048
#define DD    512
#define LL    6
#define HH    8
#define DHD   64
#define WSZ   128
#define NWIN  16
#define FFD   1365
#define TT    (BB*NN)           // 16384 tokens
#define INNER 512

#define ATTN_SMEM (2*2*WSZ*DHD*4 + 2*WSZ*4)   // ks+vs (2*256*64 f32) + km (256 i32) = 132096 B

// ---------------- scratch (static device globals; no allocation allowed) ----------------
__device__ float g_h   [TT*DD];
__device__ float g_z   [TT*DD];
__device__ float g_qkv [TT*3*INNER];
__device__ float g_o   [TT*INNER];
__device__ float g_u   [TT*2*FFD];
__device__ float g_t   [TT*FFD];
__device__ float g_pos [NN*DD];
__device__ float g_bias[HH*WSZ*2*WSZ];
__device__ float g_tab [2*WSZ*HH];

// ---------------- block reduce (128 threads) ----------------
__device__ __forceinline__ float block_sum_128(float v) {
    __shared__ float sh[4];
    int lane = threadIdx.x & 31, wid = threadIdx.x >> 5;
    #pragma unroll
    for (int o = 16; o > 0; o >>= 1) v += __shfl_xor_sync(0xffffffffu, v, o);
    __syncthreads();                    // protect sh against previous call's readers
    if (lane == 0) sh[wid] = v;
    __syncthreads();
    return sh[0] + sh[1] + sh[2] + sh[3];
}

// ---------------- LayerNorm: one block (128 thr) per token, D=512 ----------------
__global__ __launch_bounds__(128) void ln_kernel(
    const float* __restrict__ in, const float* __restrict__ g,
    const float* __restrict__ b,  float* __restrict__ out)
{
    int tok = blockIdx.x;
    const float* row = in + (size_t)tok * DD;
    int tid = threadIdx.x;
    float v[4];
    float s = 0.f;
    #pragma unroll
    for (int k = 0; k < 4; k++) { v[k] = row[tid + k*128]; s += v[k]; }
    s = block_sum_128(s);
    float mean = s * (1.f / 512.f);
    float q = 0.f;
    #pragma unroll
    for (int k = 0; k < 4; k++) { float d = v[k] - mean; q += d * d; }
    q = block_sum_128(q);
    float rstd = rsqrtf(q * (1.f / 512.f) + 1e-5f);
    float* orow = out + (size_t)tok * DD;
    #pragma unroll
    for (int k = 0; k < 4; k++) {
        int d = tid + k*128;
        orow[d] = (v[k] - mean) * rstd * g[d] + b[d];
    }
}

// ---------------- SGEMM: C[M,N] = (addC ? C : 0) + A[M,K] @ B[K,N] ----------------
// 128x128 tile, BK=8, 256 threads, 8x8 per thread. M must be a multiple of 128.
__global__ __launch_bounds__(256) void sgemm_kernel(
    const float* __restrict__ A, const float* __restrict__ B, float* __restrict__ C,
    int M, int N, int K, int addC)
{
    __shared__ float As[8][132];
    __shared__ float Bs[8][132];
    int bm = blockIdx.y << 7, bn = blockIdx.x << 7;
    int tid = threadIdx.x;
    int tx = tid & 15, ty = tid >> 4;

    float acc[8][8];
    #pragma unroll
    for (int i = 0; i < 8; i++)
        #pragma unroll
        for (int j = 0; j < 8; j++) acc[i][j] = 0.f;

    for (int k0 = 0; k0 < K; k0 += 8) {
        #pragma unroll
        for (int i = 0; i < 4; i++) {
            int e  = tid + (i << 8);
            int r  = e >> 3, c = e & 7;             // A tile 128x8
            int gc = k0 + c;
            As[c][r] = (gc < K) ? A[(size_t)(bm + r) * K + gc] : 0.f;
            int r2 = e >> 7, c2 = e & 127;          // B tile 8x128
            int gr2 = k0 + r2, gc2 = bn + c2;
            Bs[r2][c2] = (gr2 < K && gc2 < N) ? B[(size_t)gr2 * N + gc2] : 0.f;
        }
        __syncthreads();
        #pragma unroll
        for (int kk = 0; kk < 8; kk++) {
            float a[8], bb[8];
            #pragma unroll
            for (int i = 0; i < 8; i++) a[i]  = As[kk][(ty << 3) + i];
            #pragma unroll
            for (int j = 0; j < 8; j++) bb[j] = Bs[kk][(tx << 3) + j];
            #pragma unroll
            for (int i = 0; i < 8; i++)
                #pragma unroll
                for (int j = 0; j < 8; j++) acc[i][j] += a[i] * bb[j];
        }
        __syncthreads();
    }

    #pragma unroll
    for (int i = 0; i < 8; i++) {
        int row = bm + (ty << 3) + i;
        #pragma unroll
        for (int j = 0; j < 8; j++) {
            int col = bn + (tx << 3) + j;
            if (col < N) {
                size_t off = (size_t)row * N + col;
                C[off] = (addC ? C[off] : 0.f) + acc[i][j];
            }
        }
    }
}

// ---------------- positional embedding table (N, D); double sin for flag-proof accuracy ----------------
__global__ __launch_bounds__(128) void pos_kernel(float* __restrict__ pos)
{
    int n = blockIdx.x;
    for (int d = threadIdx.x; d < DD; d += 128) {
        int i = (d < 256) ? d : d - 256;
        float inv = (float)(1.0 / pow(10000.0, (double)(2 * i) / 512.0));
        float arg = (float)n * inv;          // fp32 arg like the reference
        double sv = (d < 256) ? sin((double)arg) : cos((double)arg);
        pos[n * DD + d] = (float)sv;
    }
}

// ---------------- embedding + pos add ----------------
__global__ __launch_bounds__(128) void embed_kernel(
    const int* __restrict__ x, const float* __restrict__ emb,
    const float* __restrict__ pos, float* __restrict__ h)
{
    int tok = blockIdx.x;
    int n = tok & (NN - 1);
    int xv = x[tok];
    float mk = (xv != 0) ? 1.f : 0.f;
    const float* erow = emb + (size_t)xv * DD;
    const float* prow = pos + (size_t)n * DD;
    float* hrow = h + (size_t)tok * DD;
    for (int d = threadIdx.x; d < DD; d += 128)
        hrow[d] = erow[d] * mk + prow[d];
}

// ---------------- dynamic position bias MLP: tab[2W][H] ----------------
__global__ __launch_bounds__(256) void dpb_tab_kernel(
    const float* __restrict__ w1, const float* __restrict__ b1,
    const float* __restrict__ w2, const float* __restrict__ b2,
    const float* __restrict__ w3, const float* __restrict__ b3,
    float* __restrict__ tab)
{
    int r = blockIdx.x;       // rel distance 0..255
    int c = threadIdx.x;      // 256
    __shared__ float h1[256];
    __shared__ float h2[256];
    float v = (float)r * w1[c] + b1[c];
    h1[c] = v / (1.f + expf(-v));              // silu
    __syncthreads();
    float s = b2[c];
    #pragma unroll 4
    for (int k = 0; k < 256; k++) s += h1[k] * w2[k * 256 + c];
    h2[c] = s / (1.f + expf(-s));
    __syncthreads();
    if (c < HH) {
        float t = b3[c];
        #pragma unroll 4
        for (int k = 0; k < 256; k++) t += h2[k] * w3[k * HH + c];
        tab[r * HH + c] = t;
    }
}

// ---------------- bias fill: bias[h][i][j] = tab[|i+128-j|][h] ----------------
__global__ __launch_bounds__(256) void dpb_bias_kernel(
    const float* __restrict__ tab, float* __restrict__ bias)
{
    int idx = blockIdx.x * 256 + threadIdx.x;   // 262144 total
    int hh = idx >> 15;
    int i  = (idx >> 8) & 127;
    int j  = idx & 255;
    int a  = abs(i + 128 - j);
    bias[idx] = tab[a * HH + hh];
}

// ---------------- windowed attention ----------------
// grid (NWIN, H, B), 128 threads = one query row each.
__global__ __launch_bounds__(128) void attn_kernel(
    const float* __restrict__ qkv, const int* __restrict__ x,
    const float* __restrict__ bias, float* __restrict__ o)
{
    extern __shared__ float sm[];
    float* ks = sm;                 // [256][64]
    float* vs = sm + 2*WSZ*DHD;     // [256][64]
    int*   km = (int*)(sm + 4*WSZ*DHD);
    int w = blockIdx.x, h = blockIdx.y, b = blockIdx.z;
    int tid = threadIdx.x;

    // key padding mask (and prev-window availability)
    for (int e = tid; e < 2*WSZ; e += 128) {
        int ok;
        if (e < WSZ) ok = (w > 0) ? (x[b * NN + (w - 1) * WSZ + e] != 0) : 0;
        else         ok = (x[b * NN + w * WSZ + (e - WSZ)] != 0);
        km[e] = ok;
    }
    // stage K,V (prev window pads = -1.0, matching the reference pad_value)
    for (int e = tid; e < 2*WSZ*DHD; e += 128) {
        int j = e >> 6, d = e & 63;
        float kv, vv;
        if (j < WSZ && w == 0) { kv = -1.f; vv = -1.f; }
        else {
            int tok = (j < WSZ) ? (b * NN + (w - 1) * WSZ + j)
                                : (b * NN + w * WSZ + (j - WSZ));
            size_t base = (size_t)tok * (3*INNER) + h * DHD + d;
            kv = qkv[base + INNER];
            vv = qkv[base + 2*INNER];
        }
        ks[e] = kv; vs[e] = vv;
    }
    __syncthreads();

    int i = tid;
    float q[DHD];
    {
        size_t qb = (size_t)(b * NN + w * WSZ + i) * (3*INNER) + h * DHD;
        #pragma unroll
        for (int d = 0; d < DHD; d++) q[d] = qkv[qb + d] * 0.125f;   // DH^-0.5
    }
    const float* brow = bias + ((size_t)h * WSZ + i) * (2*WSZ);

    // pass 1: row max
    float m = -FLT_MAX;
    for (int j = 0; j < 2*WSZ; j++) {
        bool valid = (j < WSZ) ? (w > 0 && j >= i && km[j])
                               : ((j - WSZ) <= i && km[j]);
        if (valid) {
            const float* kr = ks + j * DHD;
            float s0=0.f,s1=0.f,s2=0.f,s3=0.f;
            #pragma unroll
            for (int d = 0; d < DHD; d += 4) {
                s0 += q[d]   * kr[d];
                s1 += q[d+1] * kr[d+1];
                s2 += q[d+2] * kr[d+2];
                s3 += q[d+3] * kr[d+3];
            }
            float s = (s0 + s1) + (s2 + s3) + brow[j];
            m = fmaxf(m, s);
        }
    }

    // pass 2: weighted sum
    float acc[DHD];
    #pragma unroll
    for (int d = 0; d < DHD; d++) acc[d] = 0.f;
    float l = 0.f;

    if (m == -FLT_MAX) {
        // all-masked row: softmax of all-equal -> uniform 1/256 (includes -1.0 V pads)
        for (int j = 0; j < 2*WSZ; j++) {
            const float* vr = vs + j * DHD;
            #pragma unroll
            for (int d = 0; d < DHD; d++) acc[d] += vr[d];
        }
        l = 256.f;
    } else {
        for (int j = 0; j < 2*WSZ; j++) {
            bool valid = (j < WSZ) ? (w > 0 && j >= i && km[j])
                                   : ((j - WSZ) <= i && km[j]);
            if (valid) {
                const float* kr = ks + j * DHD;
                float s0=0.f,s1=0.f,s2=0.f,s3=0.f;
                #pragma unroll
                for (int d = 0; d < DHD; d += 4) {
                    s0 += q[d]   * kr[d];
                    s1 += q[d+1] * kr[d+1];
                    s2 += q[d+2] * kr[d+2];
                    s3 += q[d+3] * kr[d+3];
                }
                float s = (s0 + s1) + (s2 + s3) + brow[j];
                float p = expf(s - m);
                l += p;
                const float* vr = vs + j * DHD;
                #pragma unroll
                for (int d = 0; d < DHD; d++) acc[d] += p * vr[d];
            }
        }
    }
    float inv = 1.f / l;
    size_t ob = (size_t)(b * NN + w * WSZ + i) * INNER + h * DHD;
    #pragma unroll
    for (int d = 0; d < DHD; d++) o[ob + d] = acc[d] * inv;
}

// ---------------- GEGLU: t = a1 * gelu_exact(g1) ----------------
__global__ __launch_bounds__(256) void geglu_kernel(
    const float* __restrict__ u, float* __restrict__ t)
{
    int mrow = blockIdx.x;
    const float* ur = u + (size_t)mrow * (2*FFD);
    float* tr = t + (size_t)mrow * FFD;
    for (int f = threadIdx.x; f < FFD; f += 256) {
        float a = ur[f], g = ur[FFD + f];
        float ge = 0.5f * g * (1.f + erff(g * 0.70710678118654752f));
        tr[f] = a * ge;
    }
}

// ---------------- launch ----------------
extern "C" void kernel_launch(void* const* d_in, const int* in_sizes, int n_in,
                              void* d_out, int out_size)
{
    const int*   x        = (const int*)  d_in[0];
    const float* emb      = (const float*)d_in[1];
    const float* ln_ag    = (const float*)d_in[2];
    const float* ln_ab    = (const float*)d_in[3];
    const float* w_qkv    = (const float*)d_in[4];
    const float* w_out    = (const float*)d_in[5];
    const float* ln_fg    = (const float*)d_in[6];
    const float* ln_fb    = (const float*)d_in[7];
    const float* w_ff1    = (const float*)d_in[8];
    const float* w_ff2    = (const float*)d_in[9];
    const float* dpb_w1   = (const float*)d_in[10];
    const float* dpb_b1   = (const float*)d_in[11];
    const float* dpb_w2   = (const float*)d_in[12];
    const float* dpb_b2   = (const float*)d_in[13];
    const float* dpb_w3   = (const float*)d_in[14];
    const float* dpb_b3   = (const float*)d_in[15];
    const float* ln_og    = (const float*)d_in[16];
    const float* ln_ob    = (const float*)d_in[17];
    const float* w_logits = (const float*)d_in[18];
    float* out = (float*)d_out;

    float *h, *z, *qkv, *o, *u, *t, *pos, *bias, *tab;
    cudaGetSymbolAddress((void**)&h,    g_h);
    cudaGetSymbolAddress((void**)&z,    g_z);
    cudaGetSymbolAddress((void**)&qkv,  g_qkv);
    cudaGetSymbolAddress((void**)&o,    g_o);
    cudaGetSymbolAddress((void**)&u,    g_u);
    cudaGetSymbolAddress((void**)&t,    g_t);
    cudaGetSymbolAddress((void**)&pos,  g_pos);
    cudaGetSymbolAddress((void**)&bias, g_bias);
    cudaGetSymbolAddress((void**)&tab,  g_tab);

    cudaFuncSetAttribute(attn_kernel, cudaFuncAttributeMaxDynamicSharedMemorySize, ATTN_SMEM);

    pos_kernel   <<<NN, 128>>>(pos);
    embed_kernel <<<TT, 128>>>(x, emb, pos, h);
    dpb_tab_kernel <<<2*WSZ, 256>>>(dpb_w1, dpb_b1, dpb_w2, dpb_b2, dpb_w3, dpb_b3, tab);
    dpb_bias_kernel<<<(HH*WSZ*2*WSZ)/256, 256>>>(tab, bias);

    for (int l = 0; l < LL; l++) {
        ln_kernel<<<TT, 128>>>(h, ln_ag + (size_t)l*DD, ln_ab + (size_t)l*DD, z);
        sgemm_kernel<<<dim3(12, 128), 256>>>(z, w_qkv + (size_t)l*DD*3*INNER, qkv,
                                             TT, 3*INNER, DD, 0);
        attn_kernel<<<dim3(NWIN, HH, BB), 128, ATTN_SMEM>>>(qkv, x, bias, o);
        sgemm_kernel<<<dim3(4, 128), 256>>>(o, w_out + (size_t)l*INNER*DD, h,
                                            TT, DD, INNER, 1);
        ln_kernel<<<TT, 128>>>(h, ln_fg + (size_t)l*DD, ln_fb + (size_t)l*DD, z);
        sgemm_kernel<<<dim3(22, 128), 256>>>(z, w_ff1 + (size_t)l*DD*2*FFD, u,
                                             TT, 2*FFD, DD, 0);
        geglu_kernel<<<TT, 256>>>(u, t);
        sgemm_kernel<<<dim3(4, 128), 256>>>(t, w_ff2 + (size_t)l*FFD*DD, h,
                                            TT, DD, FFD, 1);
    }
    ln_kernel<<<TT, 128>>>(h, ln_og, ln_ob, z);
    sgemm_kernel<<<dim3(4, 128), 256>>>(z, w_logits, out, TT, DD, DD, 0);
}

// round 4
// speedup vs baseline: 2.3950x; 2.3950x over previous
#include <cuda_runtime.h>
#include <cuda_bf16.h>
#include <cstdint>
#include <math.h>
#include <float.h>

// ---------------- problem constants ----------------
#define BB    8
#define NN    2048
#define DD    512
#define LL    6
#define HH    8
#define DHD   64
#define WSZ   128
#define NWIN  16
#define FFD   1365
#define FF2   2730          // 2*FFD
#define FFP   1376          // FFD padded (/32, /16)
#define FF2P  2816          // 2*FFD padded (/128)
#define TT    (BB*NN)       // 16384 tokens
#define INNER 512

#define ATTN_SMEM (2*2*WSZ*DHD*4 + 2*WSZ*4)   // 132096 B

// ---------------- scratch (static device globals) ----------------
__device__ __align__(16) float g_h   [TT*DD];
__device__ __align__(16) float g_z   [TT*DD];
__device__ __align__(16) float g_qkv [TT*3*INNER];
__device__ __align__(16) float g_o   [TT*INNER];
__device__ __align__(16) float g_u   [(size_t)TT*FF2P];
__device__ __align__(16) float g_t   [(size_t)TT*FFP];
__device__ __align__(16) float g_pos [NN*DD];
__device__ __align__(16) float g_biasT[HH*2*WSZ*WSZ];   // [h][j][i]
__device__ __align__(16) float g_tab [2*WSZ*HH];
// padded FF weights (f32, zero-padded)
__device__ __align__(16) float g_wff1p[(size_t)LL*DD*FF2P];
__device__ __align__(16) float g_wff2p[(size_t)LL*FFP*DD];

// ---------------- tf32 helpers ----------------
__device__ __forceinline__ uint32_t f2tf32(float f) {
    uint32_t o;
    asm("cvt.rna.tf32.f32 %0, %1;" : "=r"(o) : "f"(f));
    return o;
}
__device__ __forceinline__ void mma_tf32(float* c, const uint32_t* a, uint32_t b0, uint32_t b1) {
    asm volatile(
        "mma.sync.aligned.m16n8k8.row.col.f32.tf32.tf32.f32 "
        "{%0,%1,%2,%3},{%4,%5,%6,%7},{%8,%9},{%0,%1,%2,%3};"
        : "+f"(c[0]), "+f"(c[1]), "+f"(c[2]), "+f"(c[3])
        : "r"(a[0]), "r"(a[1]), "r"(a[2]), "r"(a[3]), "r"(b0), "r"(b1));
}

// ---------------- TGEMM: C[M,N](f32) = (addC?C:0) + A[M,K](f32->tf32) @ B[K,N](f32->tf32) ----------
// M%128==0, N%128==0, K%16==0. 128x128 tile, BK=16, 256 threads, 8 warps (2Mx4N of 64x32).
#define APITCH 20
#define BPITCH 136
__global__ __launch_bounds__(256) void tgemm_kernel(
    const float* __restrict__ A, const float* __restrict__ B,
    float* __restrict__ C, int M, int N, int K, int addC)
{
    __shared__ uint32_t Asm[2][128][APITCH];
    __shared__ uint32_t Bsm[2][16][BPITCH];

    int tid = threadIdx.x, lane = tid & 31, warp = tid >> 5;
    int wm = warp & 1, wn = warp >> 1;
    int bm = blockIdx.y << 7, bn = blockIdx.x << 7;
    int gid = lane >> 2, tig = lane & 3;

    // global-load coords
    int ar = tid >> 2, ac = (tid & 3) << 2;   // A: 128x16, 2 float4/thread (rows +0,+64)
    int br = tid >> 5, bc = (tid & 31) << 2;  // B: 16x128, 2 float4/thread (rows +0,+8)

    float acc[4][4][4];
    #pragma unroll
    for (int i = 0; i < 4; i++) {
        #pragma unroll
        for (int j = 0; j < 4; j++) {
            #pragma unroll
            for (int k = 0; k < 4; k++) acc[i][j][k] = 0.f;
        }
    }

    const float* Ag = A + (size_t)bm * K;
    const float* Bg = B + bn;

    // prologue
    {
        float4 a0 = *(const float4*)(Ag + (size_t)ar * K + ac);
        float4 a1 = *(const float4*)(Ag + (size_t)(ar + 64) * K + ac);
        float4 b0 = *(const float4*)(Bg + (size_t)br * N + bc);
        float4 b1 = *(const float4*)(Bg + (size_t)(br + 8) * N + bc);
        Asm[0][ar][ac+0] = f2tf32(a0.x); Asm[0][ar][ac+1] = f2tf32(a0.y);
        Asm[0][ar][ac+2] = f2tf32(a0.z); Asm[0][ar][ac+3] = f2tf32(a0.w);
        Asm[0][ar+64][ac+0] = f2tf32(a1.x); Asm[0][ar+64][ac+1] = f2tf32(a1.y);
        Asm[0][ar+64][ac+2] = f2tf32(a1.z); Asm[0][ar+64][ac+3] = f2tf32(a1.w);
        Bsm[0][br][bc+0] = f2tf32(b0.x); Bsm[0][br][bc+1] = f2tf32(b0.y);
        Bsm[0][br][bc+2] = f2tf32(b0.z); Bsm[0][br][bc+3] = f2tf32(b0.w);
        Bsm[0][br+8][bc+0] = f2tf32(b1.x); Bsm[0][br+8][bc+1] = f2tf32(b1.y);
        Bsm[0][br+8][bc+2] = f2tf32(b1.z); Bsm[0][br+8][bc+3] = f2tf32(b1.w);
    }
    __syncthreads();

    int tiles = K >> 4;
    int buf = 0;
    for (int t = 0; t < tiles; t++) {
        float4 na0, na1, nb0, nb1;
        bool more = (t + 1 < tiles);
        if (more) {
            int k0n = (t + 1) << 4;
            na0 = *(const float4*)(Ag + (size_t)ar * K + k0n + ac);
            na1 = *(const float4*)(Ag + (size_t)(ar + 64) * K + k0n + ac);
            nb0 = *(const float4*)(Bg + (size_t)(k0n + br) * N + bc);
            nb1 = *(const float4*)(Bg + (size_t)(k0n + br + 8) * N + bc);
        }
        #pragma unroll
        for (int kk = 0; kk < 2; kk++) {
            uint32_t af[4][4];
            #pragma unroll
            for (int i = 0; i < 4; i++) {
                int r = wm*64 + i*16 + gid;
                int c = kk*8 + tig;
                af[i][0] = Asm[buf][r][c];
                af[i][1] = Asm[buf][r+8][c];
                af[i][2] = Asm[buf][r][c+4];
                af[i][3] = Asm[buf][r+8][c+4];
            }
            uint32_t bf[4][2];
            #pragma unroll
            for (int j = 0; j < 4; j++) {
                int c = wn*32 + j*8 + gid;
                int r = kk*8 + tig;
                bf[j][0] = Bsm[buf][r][c];
                bf[j][1] = Bsm[buf][r+4][c];
            }
            #pragma unroll
            for (int i = 0; i < 4; i++) {
                #pragma unroll
                for (int j = 0; j < 4; j++) {
                    mma_tf32(acc[i][j], af[i], bf[j][0], bf[j][1]);
                }
            }
        }
        if (more) {
            int nb = buf ^ 1;
            Asm[nb][ar][ac+0] = f2tf32(na0.x); Asm[nb][ar][ac+1] = f2tf32(na0.y);
            Asm[nb][ar][ac+2] = f2tf32(na0.z); Asm[nb][ar][ac+3] = f2tf32(na0.w);
            Asm[nb][ar+64][ac+0] = f2tf32(na1.x); Asm[nb][ar+64][ac+1] = f2tf32(na1.y);
            Asm[nb][ar+64][ac+2] = f2tf32(na1.z); Asm[nb][ar+64][ac+3] = f2tf32(na1.w);
            Bsm[nb][br][bc+0] = f2tf32(nb0.x); Bsm[nb][br][bc+1] = f2tf32(nb0.y);
            Bsm[nb][br][bc+2] = f2tf32(nb0.z); Bsm[nb][br][bc+3] = f2tf32(nb0.w);
            Bsm[nb][br+8][bc+0] = f2tf32(nb1.x); Bsm[nb][br+8][bc+1] = f2tf32(nb1.y);
            Bsm[nb][br+8][bc+2] = f2tf32(nb1.z); Bsm[nb][br+8][bc+3] = f2tf32(nb1.w);
        }
        __syncthreads();
        buf ^= 1;
    }

    #pragma unroll
    for (int i = 0; i < 4; i++) {
        int r0 = bm + wm*64 + i*16 + gid;
        #pragma unroll
        for (int j = 0; j < 4; j++) {
            int c0 = bn + wn*32 + j*8 + (tig << 1);
            float2* p0 = (float2*)&C[(size_t)r0 * N + c0];
            float2* p1 = (float2*)&C[(size_t)(r0 + 8) * N + c0];
            if (addC) {
                float2 v0 = *p0, v1 = *p1;
                v0.x += acc[i][j][0]; v0.y += acc[i][j][1];
                v1.x += acc[i][j][2]; v1.y += acc[i][j][3];
                *p0 = v0; *p1 = v1;
            } else {
                *p0 = make_float2(acc[i][j][0], acc[i][j][1]);
                *p1 = make_float2(acc[i][j][2], acc[i][j][3]);
            }
        }
    }
}

// ---------------- weight pad-copy f32 -> f32 (zero pad) ----------------
__global__ __launch_bounds__(256) void padw_kernel(
    const float* __restrict__ src, float* __restrict__ dst,
    int Lc, int K, int N, int Kp, int Np)
{
    size_t idx = (size_t)blockIdx.x * 256 + threadIdx.x;
    size_t total = (size_t)Lc * Kp * Np;
    if (idx >= total) return;
    int l = (int)(idx / ((size_t)Kp * Np));
    int rem = (int)(idx - (size_t)l * Kp * Np);
    int r = rem / Np, c = rem - r * Np;
    dst[idx] = (r < K && c < N) ? src[((size_t)l * K + r) * N + c] : 0.f;
}

// ---------------- block reduce (128 threads) ----------------
__device__ __forceinline__ float block_sum_128(float v) {
    __shared__ float sh[4];
    int lane = threadIdx.x & 31, wid = threadIdx.x >> 5;
    #pragma unroll
    for (int o = 16; o > 0; o >>= 1) v += __shfl_xor_sync(0xffffffffu, v, o);
    __syncthreads();
    if (lane == 0) sh[wid] = v;
    __syncthreads();
    return sh[0] + sh[1] + sh[2] + sh[3];
}

// ---------------- LayerNorm (f32 -> f32) ----------------
__global__ __launch_bounds__(128) void ln_kernel(
    const float* __restrict__ in, const float* __restrict__ g,
    const float* __restrict__ b,  float* __restrict__ out)
{
    int tok = blockIdx.x;
    const float* row = in + (size_t)tok * DD;
    int tid = threadIdx.x;
    float v[4];
    float s = 0.f;
    #pragma unroll
    for (int k = 0; k < 4; k++) { v[k] = row[tid + k*128]; s += v[k]; }
    s = block_sum_128(s);
    float mean = s * (1.f / 512.f);
    float q = 0.f;
    #pragma unroll
    for (int k = 0; k < 4; k++) { float d = v[k] - mean; q += d * d; }
    q = block_sum_128(q);
    float rstd = rsqrtf(q * (1.f / 512.f) + 1e-5f);
    float* orow = out + (size_t)tok * DD;
    #pragma unroll
    for (int k = 0; k < 4; k++) {
        int d = tid + k*128;
        orow[d] = (v[k] - mean) * rstd * g[d] + b[d];
    }
}

// ---------------- positional embedding ----------------
__global__ __launch_bounds__(128) void pos_kernel(float* __restrict__ pos)
{
    int n = blockIdx.x;
    for (int d = threadIdx.x; d < DD; d += 128) {
        int i = (d < 256) ? d : d - 256;
        float inv = (float)(1.0 / pow(10000.0, (double)(2 * i) / 512.0));
        float arg = (float)n * inv;
        double sv = (d < 256) ? sin((double)arg) : cos((double)arg);
        pos[n * DD + d] = (float)sv;
    }
}

// ---------------- embedding + pos add ----------------
__global__ __launch_bounds__(128) void embed_kernel(
    const int* __restrict__ x, const float* __restrict__ emb,
    const float* __restrict__ pos, float* __restrict__ h)
{
    int tok = blockIdx.x;
    int n = tok & (NN - 1);
    int xv = x[tok];
    float mk = (xv != 0) ? 1.f : 0.f;
    const float* erow = emb + (size_t)xv * DD;
    const float* prow = pos + (size_t)n * DD;
    float* hrow = h + (size_t)tok * DD;
    for (int d = threadIdx.x; d < DD; d += 128)
        hrow[d] = erow[d] * mk + prow[d];
}

// ---------------- dynamic position bias MLP ----------------
__global__ __launch_bounds__(256) void dpb_tab_kernel(
    const float* __restrict__ w1, const float* __restrict__ b1,
    const float* __restrict__ w2, const float* __restrict__ b2,
    const float* __restrict__ w3, const float* __restrict__ b3,
    float* __restrict__ tab)
{
    int r = blockIdx.x;
    int c = threadIdx.x;
    __shared__ float h1[256];
    __shared__ float h2[256];
    float v = (float)r * w1[c] + b1[c];
    h1[c] = v / (1.f + expf(-v));
    __syncthreads();
    float s = b2[c];
    #pragma unroll 4
    for (int k = 0; k < 256; k++) s += h1[k] * w2[k * 256 + c];
    h2[c] = s / (1.f + expf(-s));
    __syncthreads();
    if (c < HH) {
        float t = b3[c];
        #pragma unroll 4
        for (int k = 0; k < 256; k++) t += h2[k] * w3[k * HH + c];
        tab[r * HH + c] = t;
    }
}

// ---------------- bias fill, transposed: biasT[h][j][i] = tab[|i+128-j|][h] ----------------
__global__ __launch_bounds__(256) void dpb_bias_kernel(
    const float* __restrict__ tab, float* __restrict__ biasT)
{
    int idx = blockIdx.x * 256 + threadIdx.x;
    int hh = idx >> 15;
    int j  = (idx >> 7) & 255;
    int i  = idx & 127;
    int a  = abs(i + 128 - j);
    biasT[idx] = tab[a * HH + hh];
}

// ---------------- windowed attention (online softmax, f32) ----------------
__global__ __launch_bounds__(128) void attn_kernel(
    const float* __restrict__ qkv, const int* __restrict__ x,
    const float* __restrict__ biasT, float* __restrict__ o)
{
    extern __shared__ float sm[];
    float* ks = sm;                 // [256][64]
    float* vs = sm + 2*WSZ*DHD;     // [256][64]
    int*   km = (int*)(sm + 4*WSZ*DHD);
    int w = blockIdx.x, h = blockIdx.y, b = blockIdx.z;
    int tid = threadIdx.x;

    for (int e = tid; e < 2*WSZ; e += 128) {
        int ok;
        if (e < WSZ) ok = (w > 0) ? (x[b * NN + (w - 1) * WSZ + e] != 0) : 0;
        else         ok = (x[b * NN + w * WSZ + (e - WSZ)] != 0);
        km[e] = ok;
    }
    for (int e = tid; e < 2*WSZ*DHD; e += 128) {
        int j = e >> 6, d = e & 63;
        float kv, vv;
        if (j < WSZ && w == 0) { kv = -1.f; vv = -1.f; }
        else {
            int tok = (j < WSZ) ? (b * NN + (w - 1) * WSZ + j)
                                : (b * NN + w * WSZ + (j - WSZ));
            size_t base = (size_t)tok * (3*INNER) + h * DHD + d;
            kv = qkv[base + INNER];
            vv = qkv[base + 2*INNER];
        }
        ks[e] = kv; vs[e] = vv;
    }
    __syncthreads();

    int i = tid;
    float q[DHD];
    {
        size_t qb = (size_t)(b * NN + w * WSZ + i) * (3*INNER) + h * DHD;
        #pragma unroll
        for (int d = 0; d < DHD; d++) q[d] = qkv[qb + d] * 0.125f;
    }
    const float* brow = biasT + (size_t)h * 2*WSZ*WSZ + i;

    float m = -FLT_MAX, l = 0.f;
    float acc[DHD];
    #pragma unroll
    for (int d = 0; d < DHD; d++) acc[d] = 0.f;

    for (int j = 0; j < 2*WSZ; j++) {
        bool valid;
        if (j < WSZ) valid = (w > 0) && (j >= i) && (km[j] != 0);
        else         valid = ((j - WSZ) <= i) && (km[j] != 0);
        if (valid) {
            const float* kr = ks + j * DHD;
            float s0 = 0.f, s1 = 0.f, s2 = 0.f, s3 = 0.f;
            #pragma unroll
            for (int d = 0; d < DHD; d += 4) {
                s0 += q[d]   * kr[d];
                s1 += q[d+1] * kr[d+1];
                s2 += q[d+2] * kr[d+2];
                s3 += q[d+3] * kr[d+3];
            }
            float s = (s0 + s1) + (s2 + s3) + brow[(size_t)j * WSZ];
            if (s > m) {
                float cc = (m == -FLT_MAX) ? 0.f : expf(m - s);
                l *= cc;
                #pragma unroll
                for (int d = 0; d < DHD; d++) acc[d] *= cc;
                m = s;
            }
            float p = expf(s - m);
            l += p;
            const float* vr = vs + j * DHD;
            #pragma unroll
            for (int d = 0; d < DHD; d++) acc[d] += p * vr[d];
        }
    }

    if (m == -FLT_MAX) {
        #pragma unroll
        for (int d = 0; d < DHD; d++) acc[d] = 0.f;
        for (int j = 0; j < 2*WSZ; j++) {
            const float* vr = vs + j * DHD;
            #pragma unroll
            for (int d = 0; d < DHD; d++) acc[d] += vr[d];
        }
        l = 256.f;
    }
    float inv = 1.f / l;
    size_t obase = (size_t)(b * NN + w * WSZ + i) * INNER + h * DHD;
    #pragma unroll
    for (int d = 0; d < DHD; d++) o[obase + d] = acc[d] * inv;
}

// ---------------- GEGLU: t[.., FFP] = a1 * gelu_exact(g1), zero pad ----------------
__global__ __launch_bounds__(256) void geglu_kernel(
    const float* __restrict__ u, float* __restrict__ t)
{
    int mrow = blockIdx.x;
    const float* ur = u + (size_t)mrow * FF2P;
    float* tr = t + (size_t)mrow * FFP;
    for (int f = threadIdx.x; f < FFP; f += 256) {
        float r = 0.f;
        if (f < FFD) {
            float a = ur[f], g = ur[FFD + f];
            float ge = 0.5f * g * (1.f + erff(g * 0.70710678118654752f));
            r = a * ge;
        }
        tr[f] = r;
    }
}

// ---------------- launch ----------------
extern "C" void kernel_launch(void* const* d_in, const int* in_sizes, int n_in,
                              void* d_out, int out_size)
{
    const int*   x        = (const int*)  d_in[0];
    const float* emb      = (const float*)d_in[1];
    const float* ln_ag    = (const float*)d_in[2];
    const float* ln_ab    = (const float*)d_in[3];
    const float* w_qkv    = (const float*)d_in[4];
    const float* w_out    = (const float*)d_in[5];
    const float* ln_fg    = (const float*)d_in[6];
    const float* ln_fb    = (const float*)d_in[7];
    const float* w_ff1    = (const float*)d_in[8];
    const float* w_ff2    = (const float*)d_in[9];
    const float* dpb_w1   = (const float*)d_in[10];
    const float* dpb_b1   = (const float*)d_in[11];
    const float* dpb_w2   = (const float*)d_in[12];
    const float* dpb_b2   = (const float*)d_in[13];
    const float* dpb_w3   = (const float*)d_in[14];
    const float* dpb_b3   = (const float*)d_in[15];
    const float* ln_og    = (const float*)d_in[16];
    const float* ln_ob    = (const float*)d_in[17];
    const float* w_logits = (const float*)d_in[18];
    float* out = (float*)d_out;

    float *h, *z, *qkv, *o, *u, *t, *pos, *biasT, *tab, *wff1p, *wff2p;
    cudaGetSymbolAddress((void**)&h,     g_h);
    cudaGetSymbolAddress((void**)&z,     g_z);
    cudaGetSymbolAddress((void**)&qkv,   g_qkv);
    cudaGetSymbolAddress((void**)&o,     g_o);
    cudaGetSymbolAddress((void**)&u,     g_u);
    cudaGetSymbolAddress((void**)&t,     g_t);
    cudaGetSymbolAddress((void**)&pos,   g_pos);
    cudaGetSymbolAddress((void**)&biasT, g_biasT);
    cudaGetSymbolAddress((void**)&tab,   g_tab);
    cudaGetSymbolAddress((void**)&wff1p, g_wff1p);
    cudaGetSymbolAddress((void**)&wff2p, g_wff2p);

    cudaFuncSetAttribute(attn_kernel, cudaFuncAttributeMaxDynamicSharedMemorySize, ATTN_SMEM);

    pos_kernel   <<<NN, 128>>>(pos);
    embed_kernel <<<TT, 128>>>(x, emb, pos, h);
    dpb_tab_kernel <<<2*WSZ, 256>>>(dpb_w1, dpb_b1, dpb_w2, dpb_b2, dpb_w3, dpb_b3, tab);
    dpb_bias_kernel<<<(HH*WSZ*2*WSZ)/256, 256>>>(tab, biasT);

    // pad FF weights
    {
        size_t n1 = (size_t)LL * DD * FF2P;
        padw_kernel<<<(unsigned)((n1 + 255)/256), 256>>>(w_ff1, wff1p, LL, DD, FF2, DD, FF2P);
        size_t n2 = (size_t)LL * FFP * DD;
        padw_kernel<<<(unsigned)((n2 + 255)/256), 256>>>(w_ff2, wff2p, LL, FFD, DD, FFP, DD);
    }

    for (int l = 0; l < LL; l++) {
        ln_kernel<<<TT, 128>>>(h, ln_ag + (size_t)l*DD, ln_ab + (size_t)l*DD, z);
        tgemm_kernel<<<dim3(12, 128), 256>>>(z, w_qkv + (size_t)l*DD*3*INNER, qkv,
                                             TT, 3*INNER, DD, 0);
        attn_kernel<<<dim3(NWIN, HH, BB), 128, ATTN_SMEM>>>(qkv, x, biasT, o);
        tgemm_kernel<<<dim3(4, 128), 256>>>(o, w_out + (size_t)l*INNER*DD, h,
                                            TT, DD, INNER, 1);
        ln_kernel<<<TT, 128>>>(h, ln_fg + (size_t)l*DD, ln_fb + (size_t)l*DD, z);
        tgemm_kernel<<<dim3(FF2P/128, 128), 256>>>(z, wff1p + (size_t)l*DD*FF2P, u,
                                                   TT, FF2P, DD, 0);
        geglu_kernel<<<TT, 256>>>(u, t);
        tgemm_kernel<<<dim3(4, 128), 256>>>(t, wff2p + (size_t)l*FFP*DD, h,
                                            TT, DD, FFP, 1);
    }
    ln_kernel<<<TT, 128>>>(h, ln_og, ln_ob, z);
    tgemm_kernel<<<dim3(4, 128), 256>>>(z, w_logits, out, TT, DD, DD, 0);
}